// round 2
// baseline (speedup 1.0000x reference)
#include <cuda_runtime.h>

#define SQ 2048
#define DM 1024
#define NH 16
#define DH 64
#define NEGV -1e18f

// Scratch (device globals; no allocation allowed in kernel_launch)
__device__ float g_Q[SQ * DM];
__device__ float g_K[SQ * DM];
__device__ float g_V[SQ * DM];
__device__ float g_C[SQ * DM];

// ---------------------------------------------------------------------------
// NT GEMM: C[m,n] = scale * (sum_k A[m,k] * B[n,k] + bias[n])
// A: 2048x1024 row-major, B: 1024x1024 row-major, C: 2048x1024.
// BM=BN=64, BK=16, 256 threads, 4x4 outputs per thread.
// ---------------------------------------------------------------------------
__global__ __launch_bounds__(256) void gemm_nt_bias(
    const float* __restrict__ A, const float* __restrict__ B,
    const float* __restrict__ bias, float* __restrict__ C, float scale)
{
    __shared__ float As[16][64];   // [k][m]
    __shared__ float Bs[16][64];   // [k][n]
    const int tid = threadIdx.x;
    const int tx = tid & 15, ty = tid >> 4;
    const int m0 = blockIdx.y * 64, n0 = blockIdx.x * 64;
    const int lr = tid >> 2;            // 0..63 (tile row)
    const int lc = (tid & 3) * 4;       // 0,4,8,12 (k within BK)
    const float* Ap = A + (m0 + lr) * DM + lc;
    const float* Bp = B + (n0 + lr) * DM + lc;

    float acc[4][4] = {};

    for (int k0 = 0; k0 < DM; k0 += 16) {
        float4 av = *(const float4*)(Ap + k0);
        float4 bv = *(const float4*)(Bp + k0);
        __syncthreads();
        As[lc + 0][lr] = av.x; As[lc + 1][lr] = av.y;
        As[lc + 2][lr] = av.z; As[lc + 3][lr] = av.w;
        Bs[lc + 0][lr] = bv.x; Bs[lc + 1][lr] = bv.y;
        Bs[lc + 2][lr] = bv.z; Bs[lc + 3][lr] = bv.w;
        __syncthreads();
        #pragma unroll
        for (int k = 0; k < 16; k++) {
            float4 a = *(const float4*)&As[k][ty * 4];
            float4 b = *(const float4*)&Bs[k][tx * 4];
            acc[0][0] += a.x * b.x; acc[0][1] += a.x * b.y; acc[0][2] += a.x * b.z; acc[0][3] += a.x * b.w;
            acc[1][0] += a.y * b.x; acc[1][1] += a.y * b.y; acc[1][2] += a.y * b.z; acc[1][3] += a.y * b.w;
            acc[2][0] += a.z * b.x; acc[2][1] += a.z * b.y; acc[2][2] += a.z * b.z; acc[2][3] += a.z * b.w;
            acc[3][0] += a.w * b.x; acc[3][1] += a.w * b.y; acc[3][2] += a.w * b.z; acc[3][3] += a.w * b.w;
        }
    }

    float4 bb = *(const float4*)(bias + n0 + tx * 4);
    #pragma unroll
    for (int i = 0; i < 4; i++) {
        int m = m0 + ty * 4 + i;
        float4 o;
        o.x = scale * (acc[i][0] + bb.x);
        o.y = scale * (acc[i][1] + bb.y);
        o.z = scale * (acc[i][2] + bb.z);
        o.w = scale * (acc[i][3] + bb.w);
        *(float4*)(C + m * DM + n0 + tx * 4) = o;
    }
}

// ---------------------------------------------------------------------------
// scores[h,m,n] = sum_d Q[m, h*64+d] * K[n, h*64+d]; masked -> NEGV
// One block = one 64x64 tile of one head. Whole dh=64 lives in smem.
// ---------------------------------------------------------------------------
__global__ __launch_bounds__(256) void scores_kernel(
    const float* __restrict__ Q, const float* __restrict__ Km,
    const int* __restrict__ mask, float* __restrict__ attn)
{
    __shared__ float Qs[64][64];   // [k][m]
    __shared__ float Ks[64][64];   // [k][n]
    const int tid = threadIdx.x;
    const int tx = tid & 15, ty = tid >> 4;
    const int h = blockIdx.z;
    const int m0 = blockIdx.y * 64, n0 = blockIdx.x * 64;

    #pragma unroll
    for (int u = 0; u < 4; u++) {
        int f4 = u * 256 + tid;
        int r = f4 >> 4;
        int c = (f4 & 15) * 4;
        float4 qv = *(const float4*)(Q + (m0 + r) * DM + h * DH + c);
        Qs[c + 0][r] = qv.x; Qs[c + 1][r] = qv.y; Qs[c + 2][r] = qv.z; Qs[c + 3][r] = qv.w;
        float4 kv = *(const float4*)(Km + (n0 + r) * DM + h * DH + c);
        Ks[c + 0][r] = kv.x; Ks[c + 1][r] = kv.y; Ks[c + 2][r] = kv.z; Ks[c + 3][r] = kv.w;
    }
    __syncthreads();

    float acc[4][4] = {};
    #pragma unroll 16
    for (int k = 0; k < 64; k++) {
        float4 a = *(const float4*)&Qs[k][ty * 4];
        float4 b = *(const float4*)&Ks[k][tx * 4];
        acc[0][0] += a.x * b.x; acc[0][1] += a.x * b.y; acc[0][2] += a.x * b.z; acc[0][3] += a.x * b.w;
        acc[1][0] += a.y * b.x; acc[1][1] += a.y * b.y; acc[1][2] += a.y * b.z; acc[1][3] += a.y * b.w;
        acc[2][0] += a.z * b.x; acc[2][1] += a.z * b.y; acc[2][2] += a.z * b.z; acc[2][3] += a.z * b.w;
        acc[3][0] += a.w * b.x; acc[3][1] += a.w * b.y; acc[3][2] += a.w * b.z; acc[3][3] += a.w * b.w;
    }

    float* out = attn + (size_t)h * SQ * SQ;
    #pragma unroll
    for (int i = 0; i < 4; i++) {
        int m = m0 + ty * 4 + i;
        int4 mv = *(const int4*)(mask + (size_t)m * SQ + n0 + tx * 4);
        float4 o;
        o.x = mv.x ? NEGV : acc[i][0];
        o.y = mv.y ? NEGV : acc[i][1];
        o.z = mv.z ? NEGV : acc[i][2];
        o.w = mv.w ? NEGV : acc[i][3];
        *(float4*)(out + (size_t)m * SQ + n0 + tx * 4) = o;
    }
}

// ---------------------------------------------------------------------------
// In-place row softmax over attn rows of length 2048. One block per (h, q) row.
// Entire row lives in registers: 8 floats/thread.
// ---------------------------------------------------------------------------
__global__ __launch_bounds__(256) void softmax_kernel(float* __restrict__ attn)
{
    __shared__ float redm[8];
    __shared__ float reds[8];
    float* p = attn + (size_t)blockIdx.x * SQ;
    const int tid = threadIdx.x;

    float4 a = ((float4*)p)[tid];
    float4 b = ((float4*)p)[tid + 256];

    float m = fmaxf(fmaxf(fmaxf(a.x, a.y), fmaxf(a.z, a.w)),
                    fmaxf(fmaxf(b.x, b.y), fmaxf(b.z, b.w)));
    #pragma unroll
    for (int o = 16; o; o >>= 1) m = fmaxf(m, __shfl_xor_sync(0xffffffffu, m, o));
    if ((tid & 31) == 0) redm[tid >> 5] = m;
    __syncthreads();
    m = redm[0];
    #pragma unroll
    for (int i = 1; i < 8; i++) m = fmaxf(m, redm[i]);

    a.x = __expf(a.x - m); a.y = __expf(a.y - m); a.z = __expf(a.z - m); a.w = __expf(a.w - m);
    b.x = __expf(b.x - m); b.y = __expf(b.y - m); b.z = __expf(b.z - m); b.w = __expf(b.w - m);

    float s = (a.x + a.y) + (a.z + a.w) + (b.x + b.y) + (b.z + b.w);
    #pragma unroll
    for (int o = 16; o; o >>= 1) s += __shfl_xor_sync(0xffffffffu, s, o);
    if ((tid & 31) == 0) reds[tid >> 5] = s;
    __syncthreads();
    s = reds[0];
    #pragma unroll
    for (int i = 1; i < 8; i++) s += reds[i];

    float inv = 1.0f / s;
    a.x *= inv; a.y *= inv; a.z *= inv; a.w *= inv;
    b.x *= inv; b.y *= inv; b.z *= inv; b.w *= inv;

    ((float4*)p)[tid] = a;
    ((float4*)p)[tid + 256] = b;
}

// ---------------------------------------------------------------------------
// ctx[m, h*64+n] = sum_k attn[h,m,k] * V[k, h*64+n]   (NN GEMM, K=2048, N=64)
// ---------------------------------------------------------------------------
__global__ __launch_bounds__(256) void av_kernel(
    const float* __restrict__ attn, const float* __restrict__ V,
    float* __restrict__ ctx)
{
    __shared__ float Ps[32][64];   // [k][m]
    __shared__ float Vs[32][64];   // [k][n]
    const int tid = threadIdx.x;
    const int tx = tid & 15, ty = tid >> 4;
    const int h = blockIdx.y;
    const int m0 = blockIdx.x * 64;
    const float* P = attn + (size_t)h * SQ * SQ;

    float acc[4][4] = {};

    for (int k0 = 0; k0 < SQ; k0 += 32) {
        float4 pv[2], vv[2];
        #pragma unroll
        for (int u = 0; u < 2; u++) {
            int f4 = u * 256 + tid;
            int r = f4 >> 3, c = (f4 & 7) * 4;        // P tile: 64 rows x 8 float4
            pv[u] = *(const float4*)(P + (size_t)(m0 + r) * SQ + k0 + c);
            int vr = f4 >> 4, vc = (f4 & 15) * 4;     // V tile: 32 rows x 16 float4
            vv[u] = *(const float4*)(V + (k0 + vr) * DM + h * DH + vc);
        }
        __syncthreads();
        #pragma unroll
        for (int u = 0; u < 2; u++) {
            int f4 = u * 256 + tid;
            int r = f4 >> 3, c = (f4 & 7) * 4;
            Ps[c + 0][r] = pv[u].x; Ps[c + 1][r] = pv[u].y;
            Ps[c + 2][r] = pv[u].z; Ps[c + 3][r] = pv[u].w;
            int vr = f4 >> 4, vc = (f4 & 15) * 4;
            *(float4*)&Vs[vr][vc] = vv[u];
        }
        __syncthreads();
        #pragma unroll
        for (int k = 0; k < 32; k++) {
            float4 a = *(const float4*)&Ps[k][ty * 4];
            float4 b = *(const float4*)&Vs[k][tx * 4];
            acc[0][0] += a.x * b.x; acc[0][1] += a.x * b.y; acc[0][2] += a.x * b.z; acc[0][3] += a.x * b.w;
            acc[1][0] += a.y * b.x; acc[1][1] += a.y * b.y; acc[1][2] += a.y * b.z; acc[1][3] += a.y * b.w;
            acc[2][0] += a.z * b.x; acc[2][1] += a.z * b.y; acc[2][2] += a.z * b.z; acc[2][3] += a.z * b.w;
            acc[3][0] += a.w * b.x; acc[3][1] += a.w * b.y; acc[3][2] += a.w * b.z; acc[3][3] += a.w * b.w;
        }
    }

    #pragma unroll
    for (int i = 0; i < 4; i++) {
        int m = m0 + ty * 4 + i;
        float4 o = make_float4(acc[i][0], acc[i][1], acc[i][2], acc[i][3]);
        *(float4*)(ctx + m * DM + h * DH + tx * 4) = o;
    }
}

// ---------------------------------------------------------------------------
extern "C" void kernel_launch(void* const* d_in, const int* in_sizes, int n_in,
                              void* d_out, int out_size)
{
    const float* X    = (const float*)d_in[0];
    const int*   mask = (const int*)d_in[1];   // bool -> 32-bit (int32 or f32); !=0 works for both
    const float* Wq   = (const float*)d_in[2];
    const float* bq   = (const float*)d_in[3];
    const float* Wk   = (const float*)d_in[4];
    const float* bk   = (const float*)d_in[5];
    const float* Wv   = (const float*)d_in[6];
    const float* bv   = (const float*)d_in[7];
    const float* Wo   = (const float*)d_in[8];
    const float* bo   = (const float*)d_in[9];

    float* out  = (float*)d_out;                 // (S, D)
    float* attn = out + (size_t)SQ * DM;         // (H, S, S)

    float *Qb, *Kb, *Vb, *Cb;
    cudaGetSymbolAddress((void**)&Qb, g_Q);
    cudaGetSymbolAddress((void**)&Kb, g_K);
    cudaGetSymbolAddress((void**)&Vb, g_V);
    cudaGetSymbolAddress((void**)&Cb, g_C);

    dim3 thr(256);
    // QKV projections (scale 1/sqrt(64) folded into Q)
    gemm_nt_bias<<<dim3(16, 32), thr>>>(X, Wq, bq, Qb, 0.125f);
    gemm_nt_bias<<<dim3(16, 32), thr>>>(X, Wk, bk, Kb, 1.0f);
    gemm_nt_bias<<<dim3(16, 32), thr>>>(X, Wv, bv, Vb, 1.0f);
    // scores + mask -> attn region of d_out
    scores_kernel<<<dim3(32, 32, 16), thr>>>(Qb, Kb, mask, attn);
    // softmax in place
    softmax_kernel<<<NH * SQ, thr>>>(attn);
    // ctx = attn @ V
    av_kernel<<<dim3(32, 16), thr>>>(attn, Vb, Cb);
    // out = ctx @ Wo^T + bo
    gemm_nt_bias<<<dim3(16, 32), thr>>>(Cb, Wo, bo, out, 1.0f);
}

// round 3
// speedup vs baseline: 1.6044x; 1.6044x over previous
#include <cuda_runtime.h>

#define SQ 2048
#define DM 1024
#define NH 16
#define DH 64
#define NEGV -1e18f

// Scratch (device globals; no allocation allowed)
__device__ float g_Q[SQ * DM];
__device__ float g_K[SQ * DM];
__device__ float g_V[SQ * DM];
__device__ float g_C[SQ * DM];

struct Proj3 {
    const float* W[3];
    const float* bias[3];
    float* C[3];
    float scale[3];
};

// ---------------------------------------------------------------------------
// NT GEMM, 128x128 tile, BK=8, 256 threads, 8x8 per thread (split +-64).
// C[m,n] = scale * (sum_k A[m,k]*B[n,k] + bias[n]).  K = DM = 1024.
// grid.z selects one of up to 3 (W, bias, C, scale) sets.
// ---------------------------------------------------------------------------
__global__ __launch_bounds__(256) void gemm_nt_128(const float* __restrict__ A, Proj3 args)
{
    const int z = blockIdx.z;
    const float* __restrict__ B    = args.W[z];
    const float* __restrict__ bias = args.bias[z];
    float* __restrict__ C          = args.C[z];
    const float scale              = args.scale[z];

    __shared__ float As[8][132];
    __shared__ float Bs[8][132];
    const int tid = threadIdx.x;
    const int tx = tid & 15, ty = tid >> 4;
    const int m0 = blockIdx.y * 128, n0 = blockIdx.x * 128;
    const int lr = tid >> 1;          // 0..127
    const int lc = (tid & 1) * 4;     // 0 or 4
    const float* Ap = A + (size_t)(m0 + lr) * DM + lc;
    const float* Bp = B + (size_t)(n0 + lr) * DM + lc;

    float acc[8][8] = {};
    float4 ra = *(const float4*)Ap;
    float4 rb = *(const float4*)Bp;

    for (int k0 = 0; k0 < DM; k0 += 8) {
        __syncthreads();
        As[lc+0][lr]=ra.x; As[lc+1][lr]=ra.y; As[lc+2][lr]=ra.z; As[lc+3][lr]=ra.w;
        Bs[lc+0][lr]=rb.x; Bs[lc+1][lr]=rb.y; Bs[lc+2][lr]=rb.z; Bs[lc+3][lr]=rb.w;
        __syncthreads();
        if (k0 + 8 < DM) {
            ra = *(const float4*)(Ap + k0 + 8);
            rb = *(const float4*)(Bp + k0 + 8);
        }
        #pragma unroll
        for (int k = 0; k < 8; k++) {
            float4 a0 = *(const float4*)&As[k][ty*4];
            float4 a1 = *(const float4*)&As[k][64 + ty*4];
            float4 b0 = *(const float4*)&Bs[k][tx*4];
            float4 b1 = *(const float4*)&Bs[k][64 + tx*4];
            float a[8] = {a0.x,a0.y,a0.z,a0.w, a1.x,a1.y,a1.z,a1.w};
            float b[8] = {b0.x,b0.y,b0.z,b0.w, b1.x,b1.y,b1.z,b1.w};
            #pragma unroll
            for (int i = 0; i < 8; i++)
                #pragma unroll
                for (int j = 0; j < 8; j++)
                    acc[i][j] += a[i] * b[j];
        }
    }

    float4 bb0 = *(const float4*)(bias + n0 + tx*4);
    float4 bb1 = *(const float4*)(bias + n0 + 64 + tx*4);
    #pragma unroll
    for (int i = 0; i < 8; i++) {
        int m = m0 + (i < 4 ? ty*4 + i : 64 + ty*4 + (i-4));
        float* Cr = C + (size_t)m * DM + n0;
        float4 o0, o1;
        o0.x = scale*(acc[i][0]+bb0.x); o0.y = scale*(acc[i][1]+bb0.y);
        o0.z = scale*(acc[i][2]+bb0.z); o0.w = scale*(acc[i][3]+bb0.w);
        o1.x = scale*(acc[i][4]+bb1.x); o1.y = scale*(acc[i][5]+bb1.y);
        o1.z = scale*(acc[i][6]+bb1.z); o1.w = scale*(acc[i][7]+bb1.w);
        *(float4*)(Cr + tx*4)      = o0;
        *(float4*)(Cr + 64 + tx*4) = o1;
    }
}

// ---------------------------------------------------------------------------
// scores[h,m,n] = sum_d Q[m,h*64+d]*K[n,h*64+d]; masked -> NEGV.
// 128x128 tile, K-loop = 64 (BK=8), 256 threads, 8x8 per thread.
// ---------------------------------------------------------------------------
__global__ __launch_bounds__(256) void scores_128(
    const float* __restrict__ Q, const float* __restrict__ Km,
    const int* __restrict__ mask, float* __restrict__ attn)
{
    __shared__ float As[8][132];
    __shared__ float Bs[8][132];
    const int tid = threadIdx.x;
    const int tx = tid & 15, ty = tid >> 4;
    const int h = blockIdx.z;
    const int m0 = blockIdx.y * 128, n0 = blockIdx.x * 128;
    const int lr = tid >> 1;
    const int lc = (tid & 1) * 4;
    const float* Ap = Q  + (size_t)(m0 + lr) * DM + h*DH + lc;
    const float* Bp = Km + (size_t)(n0 + lr) * DM + h*DH + lc;

    float acc[8][8] = {};
    float4 ra = *(const float4*)Ap;
    float4 rb = *(const float4*)Bp;

    for (int k0 = 0; k0 < DH; k0 += 8) {
        __syncthreads();
        As[lc+0][lr]=ra.x; As[lc+1][lr]=ra.y; As[lc+2][lr]=ra.z; As[lc+3][lr]=ra.w;
        Bs[lc+0][lr]=rb.x; Bs[lc+1][lr]=rb.y; Bs[lc+2][lr]=rb.z; Bs[lc+3][lr]=rb.w;
        __syncthreads();
        if (k0 + 8 < DH) {
            ra = *(const float4*)(Ap + k0 + 8);
            rb = *(const float4*)(Bp + k0 + 8);
        }
        #pragma unroll
        for (int k = 0; k < 8; k++) {
            float4 a0 = *(const float4*)&As[k][ty*4];
            float4 a1 = *(const float4*)&As[k][64 + ty*4];
            float4 b0 = *(const float4*)&Bs[k][tx*4];
            float4 b1 = *(const float4*)&Bs[k][64 + tx*4];
            float a[8] = {a0.x,a0.y,a0.z,a0.w, a1.x,a1.y,a1.z,a1.w};
            float b[8] = {b0.x,b0.y,b0.z,b0.w, b1.x,b1.y,b1.z,b1.w};
            #pragma unroll
            for (int i = 0; i < 8; i++)
                #pragma unroll
                for (int j = 0; j < 8; j++)
                    acc[i][j] += a[i] * b[j];
        }
    }

    float* out = attn + (size_t)h * SQ * SQ;
    #pragma unroll
    for (int i = 0; i < 8; i++) {
        int m = m0 + (i < 4 ? ty*4 + i : 64 + ty*4 + (i-4));
        const int* mr = mask + (size_t)m * SQ + n0;
        float* orow = out + (size_t)m * SQ + n0;
        int4 mv0 = *(const int4*)(mr + tx*4);
        int4 mv1 = *(const int4*)(mr + 64 + tx*4);
        float4 o0, o1;
        o0.x = mv0.x ? NEGV : acc[i][0]; o0.y = mv0.y ? NEGV : acc[i][1];
        o0.z = mv0.z ? NEGV : acc[i][2]; o0.w = mv0.w ? NEGV : acc[i][3];
        o1.x = mv1.x ? NEGV : acc[i][4]; o1.y = mv1.y ? NEGV : acc[i][5];
        o1.z = mv1.z ? NEGV : acc[i][6]; o1.w = mv1.w ? NEGV : acc[i][7];
        *(float4*)(orow + tx*4)      = o0;
        *(float4*)(orow + 64 + tx*4) = o1;
    }
}

// ---------------------------------------------------------------------------
// In-place row softmax (rows of 2048). One block per (h,q) row.
// ---------------------------------------------------------------------------
__global__ __launch_bounds__(256) void softmax_kernel(float* __restrict__ attn)
{
    __shared__ float redm[8];
    __shared__ float reds[8];
    float* p = attn + (size_t)blockIdx.x * SQ;
    const int tid = threadIdx.x;

    float4 a = ((float4*)p)[tid];
    float4 b = ((float4*)p)[tid + 256];

    float m = fmaxf(fmaxf(fmaxf(a.x, a.y), fmaxf(a.z, a.w)),
                    fmaxf(fmaxf(b.x, b.y), fmaxf(b.z, b.w)));
    #pragma unroll
    for (int o = 16; o; o >>= 1) m = fmaxf(m, __shfl_xor_sync(0xffffffffu, m, o));
    if ((tid & 31) == 0) redm[tid >> 5] = m;
    __syncthreads();
    m = redm[0];
    #pragma unroll
    for (int i = 1; i < 8; i++) m = fmaxf(m, redm[i]);

    a.x = __expf(a.x - m); a.y = __expf(a.y - m); a.z = __expf(a.z - m); a.w = __expf(a.w - m);
    b.x = __expf(b.x - m); b.y = __expf(b.y - m); b.z = __expf(b.z - m); b.w = __expf(b.w - m);

    float s = (a.x + a.y) + (a.z + a.w) + (b.x + b.y) + (b.z + b.w);
    #pragma unroll
    for (int o = 16; o; o >>= 1) s += __shfl_xor_sync(0xffffffffu, s, o);
    if ((tid & 31) == 0) reds[tid >> 5] = s;
    __syncthreads();
    s = reds[0];
    #pragma unroll
    for (int i = 1; i < 8; i++) s += reds[i];

    float inv = 1.0f / s;
    a.x *= inv; a.y *= inv; a.z *= inv; a.w *= inv;
    b.x *= inv; b.y *= inv; b.z *= inv; b.w *= inv;

    ((float4*)p)[tid] = a;
    ((float4*)p)[tid + 256] = b;
}

// ---------------------------------------------------------------------------
// ctx[m, h*64+n] = sum_k attn[h,m,k]*V[k, h*64+n].
// 128x64 tile, BK=16, 128 threads, 8x8 per thread (rows +-64, cols +-32).
// ---------------------------------------------------------------------------
__global__ __launch_bounds__(128) void av_128(
    const float* __restrict__ attn, const float* __restrict__ V,
    float* __restrict__ ctx)
{
    __shared__ float Ps[16][132];
    __shared__ float Vs[16][64];
    const int tid = threadIdx.x;
    const int tx = tid & 7, ty = tid >> 3;   // 8 x 16
    const int h = blockIdx.y;
    const int m0 = blockIdx.x * 128;
    const float* P  = attn + (size_t)h * SQ * SQ;
    const float* Vb = V + h * DH;

    const int pr = tid >> 2;          // 0..31
    const int pc = (tid & 3) * 4;     // 0..12
    const int vr = tid >> 4;          // 0..7
    const int vc = (tid & 15) * 4;    // 0..60

    float acc[8][8] = {};
    float4 rp[4], rv[2];
    #pragma unroll
    for (int u = 0; u < 4; u++)
        rp[u] = *(const float4*)(P + (size_t)(m0 + pr + u*32) * SQ + pc);
    #pragma unroll
    for (int u = 0; u < 2; u++)
        rv[u] = *(const float4*)(Vb + (size_t)(vr + u*8) * DM + vc);

    for (int k0 = 0; k0 < SQ; k0 += 16) {
        __syncthreads();
        #pragma unroll
        for (int u = 0; u < 4; u++) {
            int r = pr + u*32;
            Ps[pc+0][r]=rp[u].x; Ps[pc+1][r]=rp[u].y;
            Ps[pc+2][r]=rp[u].z; Ps[pc+3][r]=rp[u].w;
        }
        #pragma unroll
        for (int u = 0; u < 2; u++)
            *(float4*)&Vs[vr + u*8][vc] = rv[u];
        __syncthreads();
        if (k0 + 16 < SQ) {
            #pragma unroll
            for (int u = 0; u < 4; u++)
                rp[u] = *(const float4*)(P + (size_t)(m0 + pr + u*32) * SQ + k0 + 16 + pc);
            #pragma unroll
            for (int u = 0; u < 2; u++)
                rv[u] = *(const float4*)(Vb + (size_t)(k0 + 16 + vr + u*8) * DM + vc);
        }
        #pragma unroll
        for (int k = 0; k < 16; k++) {
            float4 a0 = *(const float4*)&Ps[k][ty*4];
            float4 a1 = *(const float4*)&Ps[k][64 + ty*4];
            float4 b0 = *(const float4*)&Vs[k][tx*4];
            float4 b1 = *(const float4*)&Vs[k][32 + tx*4];
            float a[8] = {a0.x,a0.y,a0.z,a0.w, a1.x,a1.y,a1.z,a1.w};
            float b[8] = {b0.x,b0.y,b0.z,b0.w, b1.x,b1.y,b1.z,b1.w};
            #pragma unroll
            for (int i = 0; i < 8; i++)
                #pragma unroll
                for (int j = 0; j < 8; j++)
                    acc[i][j] += a[i] * b[j];
        }
    }

    #pragma unroll
    for (int i = 0; i < 8; i++) {
        int m = m0 + (i < 4 ? ty*4 + i : 64 + ty*4 + (i-4));
        float* Cr = ctx + (size_t)m * DM + h * DH;
        float4 o0 = make_float4(acc[i][0], acc[i][1], acc[i][2], acc[i][3]);
        float4 o1 = make_float4(acc[i][4], acc[i][5], acc[i][6], acc[i][7]);
        *(float4*)(Cr + tx*4)      = o0;
        *(float4*)(Cr + 32 + tx*4) = o1;
    }
}

// ---------------------------------------------------------------------------
extern "C" void kernel_launch(void* const* d_in, const int* in_sizes, int n_in,
                              void* d_out, int out_size)
{
    const float* X    = (const float*)d_in[0];
    const int*   mask = (const int*)d_in[1];
    const float* Wq   = (const float*)d_in[2];
    const float* bq   = (const float*)d_in[3];
    const float* Wk   = (const float*)d_in[4];
    const float* bk   = (const float*)d_in[5];
    const float* Wv   = (const float*)d_in[6];
    const float* bv   = (const float*)d_in[7];
    const float* Wo   = (const float*)d_in[8];
    const float* bo   = (const float*)d_in[9];

    float* out  = (float*)d_out;                 // (S, D)
    float* attn = out + (size_t)SQ * DM;         // (H, S, S)

    float *Qb, *Kb, *Vb, *Cb;
    cudaGetSymbolAddress((void**)&Qb, g_Q);
    cudaGetSymbolAddress((void**)&Kb, g_K);
    cudaGetSymbolAddress((void**)&Vb, g_V);
    cudaGetSymbolAddress((void**)&Cb, g_C);

    // QKV projections fused into one launch (scale 1/8 folded into Q)
    Proj3 pa;
    pa.W[0]=Wq; pa.W[1]=Wk; pa.W[2]=Wv;
    pa.bias[0]=bq; pa.bias[1]=bk; pa.bias[2]=bv;
    pa.C[0]=Qb; pa.C[1]=Kb; pa.C[2]=Vb;
    pa.scale[0]=0.125f; pa.scale[1]=1.0f; pa.scale[2]=1.0f;
    gemm_nt_128<<<dim3(8, 16, 3), 256>>>(X, pa);

    scores_128<<<dim3(16, 16, 16), 256>>>(Qb, Kb, mask, attn);
    softmax_kernel<<<NH * SQ, 256>>>(attn);
    av_128<<<dim3(16, 16), 128>>>(attn, Vb, Cb);

    Proj3 po;
    po.W[0]=Wo; po.W[1]=Wo; po.W[2]=Wo;
    po.bias[0]=bo; po.bias[1]=bo; po.bias[2]=bo;
    po.C[0]=out; po.C[1]=out; po.C[2]=out;
    po.scale[0]=1.0f; po.scale[1]=1.0f; po.scale[2]=1.0f;
    gemm_nt_128<<<dim3(8, 16, 1), 256>>>(Cb, po);
}